// round 1
// baseline (speedup 1.0000x reference)
#include <cuda_runtime.h>
#include <math.h>

#define N_NODES 8192
#define DIN     512
#define DOUT    256
#define MAXN    1024   // max neighbors captured per row (actual max ~70)

// Scratch (device globals: allocation-free per harness rules)
__device__ float g_h[(size_t)N_NODES * DOUT];   // 8 MB
__device__ float g_g1[N_NODES];
__device__ float g_g2[N_NODES];

// ---------------------------------------------------------------------------
// Kernel A: h = elu(x) @ W1 + b1     (M=8192, K=512, N=256, fp32 SIMT)
// Tile: 128(M) x 64(N), BK=16, 256 threads, 8x4 accum per thread.
// ---------------------------------------------------------------------------
#define BM 128
#define BN 64
#define BK 16

__global__ void __launch_bounds__(256, 2)
gemm_elu_kernel(const float* __restrict__ X,
                const float* __restrict__ W,
                const float* __restrict__ b)
{
    __shared__ float As[BK][BM];   // transposed A tile
    __shared__ float Bs[BK][BN];

    const int t  = threadIdx.x;
    const int tx = t & 15;         // 0..15 -> N direction (4 cols each)
    const int ty = t >> 4;         // 0..15 -> M direction (8 rows each)
    const int m0 = blockIdx.y * BM;
    const int n0 = blockIdx.x * BN;

    float acc[8][4];
#pragma unroll
    for (int i = 0; i < 8; i++)
#pragma unroll
        for (int j = 0; j < 4; j++) acc[i][j] = 0.f;

    for (int kt = 0; kt < DIN; kt += BK) {
        // Load A tile (128x16) = 512 float4, 2 per thread, apply ELU.
#pragma unroll
        for (int u = 0; u < 2; u++) {
            int f = t + u * 256;
            int i = f >> 2;             // row in tile 0..127
            int j = (f & 3) << 2;       // k offset 0,4,8,12
            float4 v = *(const float4*)(X + (size_t)(m0 + i) * DIN + kt + j);
            v.x = v.x > 0.f ? v.x : expm1f(v.x);
            v.y = v.y > 0.f ? v.y : expm1f(v.y);
            v.z = v.z > 0.f ? v.z : expm1f(v.z);
            v.w = v.w > 0.f ? v.w : expm1f(v.w);
            As[j + 0][i] = v.x;
            As[j + 1][i] = v.y;
            As[j + 2][i] = v.z;
            As[j + 3][i] = v.w;
        }
        // Load B tile (16x64) = 256 float4, 1 per thread.
        {
            int i = t >> 4;             // k row 0..15
            int j = (t & 15) << 2;      // col 0..60
            *(float4*)&Bs[i][j] =
                *(const float4*)(W + (size_t)(kt + i) * DOUT + n0 + j);
        }
        __syncthreads();

#pragma unroll
        for (int kk = 0; kk < BK; kk++) {
            float a[8], bb[4];
            *(float4*)(a + 0) = *(const float4*)&As[kk][ty * 8 + 0];
            *(float4*)(a + 4) = *(const float4*)&As[kk][ty * 8 + 4];
            *(float4*)(bb)    = *(const float4*)&Bs[kk][tx * 4];
#pragma unroll
            for (int i = 0; i < 8; i++)
#pragma unroll
                for (int j = 0; j < 4; j++)
                    acc[i][j] = fmaf(a[i], bb[j], acc[i][j]);
        }
        __syncthreads();
    }

    // Epilogue: + bias, write h
    float4 bias = *(const float4*)(b + n0 + tx * 4);
#pragma unroll
    for (int i = 0; i < 8; i++) {
        float4 o;
        o.x = acc[i][0] + bias.x;
        o.y = acc[i][1] + bias.y;
        o.z = acc[i][2] + bias.z;
        o.w = acc[i][3] + bias.w;
        *(float4*)&g_h[(size_t)(m0 + ty * 8 + i) * DOUT + n0 + tx * 4] = o;
    }
}

// ---------------------------------------------------------------------------
// Kernel G: g1[i] = h[i]·a1_w + a1_b ; g2[i] = h[i]·a2_w + a2_b
// One warp per row; 8 warps/block, 1024 blocks.
// ---------------------------------------------------------------------------
__global__ void g_kernel(const float* __restrict__ a1w, const float* __restrict__ a1b,
                         const float* __restrict__ a2w, const float* __restrict__ a2b)
{
    int warp = threadIdx.x >> 5;
    int lane = threadIdx.x & 31;
    int r = blockIdx.x * 8 + warp;
    const float* hr = g_h + (size_t)r * DOUT;
    float s1 = 0.f, s2 = 0.f;
#pragma unroll
    for (int c = lane; c < DOUT; c += 32) {
        float hv = hr[c];
        s1 = fmaf(hv, a1w[c], s1);
        s2 = fmaf(hv, a2w[c], s2);
    }
#pragma unroll
    for (int o = 16; o; o >>= 1) {
        s1 += __shfl_xor_sync(0xffffffffu, s1, o);
        s2 += __shfl_xor_sync(0xffffffffu, s2, o);
    }
    if (lane == 0) {
        g_g1[r] = s1 + a1b[0];
        g_g2[r] = s2 + a2b[0];
    }
}

// ---------------------------------------------------------------------------
// Kernel B: per-row masked softmax + sparse aggregation.
// One block (256 threads) per row i. Scans adj row (32 KB), builds neighbor
// list in SMEM, softmax over e = leaky_relu(g2[i]+g1[j], 0.2), then
// out[i] = sum_k att_k * h[j_k].
// ---------------------------------------------------------------------------
__global__ void __launch_bounds__(256)
attn_kernel(const float* __restrict__ adj, float* __restrict__ out)
{
    __shared__ int   s_idx[MAXN];
    __shared__ float s_e[MAXN];
    __shared__ int   s_cnt;
    __shared__ float red[256];

    const int i = blockIdx.x;
    const int t = threadIdx.x;

    if (t == 0) s_cnt = 0;
    __syncthreads();

    const float g2i = g_g2[i];
    const float4* row = (const float4*)(adj + (size_t)i * N_NODES);

#pragma unroll
    for (int u = 0; u < 8; u++) {
        int f = t + u * 256;           // float4 index
        float4 v = row[f];
        int jb = f << 2;
        if (v.x > 0.f) { int p = atomicAdd(&s_cnt, 1); if (p < MAXN) { float s = g2i + g_g1[jb + 0]; s_idx[p] = jb + 0; s_e[p] = s > 0.f ? s : 0.2f * s; } }
        if (v.y > 0.f) { int p = atomicAdd(&s_cnt, 1); if (p < MAXN) { float s = g2i + g_g1[jb + 1]; s_idx[p] = jb + 1; s_e[p] = s > 0.f ? s : 0.2f * s; } }
        if (v.z > 0.f) { int p = atomicAdd(&s_cnt, 1); if (p < MAXN) { float s = g2i + g_g1[jb + 2]; s_idx[p] = jb + 2; s_e[p] = s > 0.f ? s : 0.2f * s; } }
        if (v.w > 0.f) { int p = atomicAdd(&s_cnt, 1); if (p < MAXN) { float s = g2i + g_g1[jb + 3]; s_idx[p] = jb + 3; s_e[p] = s > 0.f ? s : 0.2f * s; } }
    }
    __syncthreads();

    int cnt = s_cnt < MAXN ? s_cnt : MAXN;

    if (cnt == 0) {
        // Softmax over an all -9e15 row is uniform -> output = column-mean of h.
        float acc = 0.f;
        for (int r = 0; r < N_NODES; r++) acc += g_h[(size_t)r * DOUT + t];
        out[(size_t)i * DOUT + t] = acc * (1.f / (float)N_NODES);
        return; // uniform branch: all threads in the block take it together
    }

    // --- row max ---
    float m = -INFINITY;
    for (int k = t; k < cnt; k += 256) m = fmaxf(m, s_e[k]);
    red[t] = m;
    __syncthreads();
#pragma unroll
    for (int o = 128; o; o >>= 1) {
        if (t < o) red[t] = fmaxf(red[t], red[t + o]);
        __syncthreads();
    }
    const float rowmax = red[0];
    __syncthreads();

    // --- exp + sum ---
    float ssum = 0.f;
    for (int k = t; k < cnt; k += 256) {
        float w = __expf(s_e[k] - rowmax);
        s_e[k] = w;
        ssum += w;
    }
    red[t] = ssum;
    __syncthreads();
#pragma unroll
    for (int o = 128; o; o >>= 1) {
        if (t < o) red[t] += red[t + o];
        __syncthreads();
    }
    const float inv = 1.f / red[0];

    // --- aggregation: thread t = output channel ---
    float acc = 0.f;
    for (int k = 0; k < cnt; k++)
        acc = fmaf(s_e[k], g_h[(size_t)s_idx[k] * DOUT + t], acc);
    out[(size_t)i * DOUT + t] = acc * inv;
}

// ---------------------------------------------------------------------------
extern "C" void kernel_launch(void* const* d_in, const int* in_sizes, int n_in,
                              void* d_out, int out_size)
{
    const float* x   = (const float*)d_in[0];   // [8192, 512]
    const float* adj = (const float*)d_in[1];   // [8192, 8192]
    const float* W1  = (const float*)d_in[2];   // [512, 256]
    const float* b1  = (const float*)d_in[3];   // [256]
    const float* a1w = (const float*)d_in[4];   // [256]
    const float* a1b = (const float*)d_in[5];   // scalar
    const float* a2w = (const float*)d_in[6];   // [256]
    const float* a2b = (const float*)d_in[7];   // scalar
    float* out = (float*)d_out;                 // [8192, 256]

    dim3 gemm_grid(DOUT / BN, N_NODES / BM);    // (4, 64)
    gemm_elu_kernel<<<gemm_grid, 256>>>(x, W1, b1);

    g_kernel<<<N_NODES / 8, 256>>>(a1w, a1b, a2w, a2b);

    attn_kernel<<<N_NODES, 256>>>(adj, out);
}